// round 14
// baseline (speedup 1.0000x reference)
#include <cuda_runtime.h>
#include <math.h>

#define BV 48
#define BT 48
#define MW 32
#define NT 196
#define CD 512
#define HIDN 102
#define NKEEP 98
#define NSEL 39
#define NTOKS 41
#define NPAIR (BT*BV)
#define NTOK (BV*NT)

typedef unsigned long long ull;

// ---------------- scratch (device globals) ----------------------------------
__device__ float g_capn[BT*MW*CD];
__device__ float g_spn[BV*NT*CD];
__device__ float g_sim[BV*NT];
__device__ float g_score[NPAIR*NT];
__device__ int   g_keep[NPAIR*NKEEP];
__device__ float g_extra[NPAIR*CD];
__device__ float g_tmu[NTOK];
__device__ float g_trstd[NTOK];
__device__ float g_h[(size_t)NTOK*HIDN];
__device__ float g_tlog[(size_t)NTOK*NSEL];
__device__ float g_wt[(size_t)NPAIR*NKEEP*NSEL];
__device__ float g_toks[(size_t)NPAIR*NTOKS*CD];

__device__ __forceinline__ float warpSum(float v){
  #pragma unroll
  for (int o=16;o;o>>=1) v += __shfl_xor_sync(0xffffffffu, v, o);
  return v;
}
__device__ __forceinline__ float warpMax(float v){
  #pragma unroll
  for (int o=16;o;o>>=1) v = fmaxf(v, __shfl_xor_sync(0xffffffffu, v, o));
  return v;
}
__device__ __forceinline__ ull pk2(float lo, float hi){
  ull r; asm("mov.b64 %0, {%1,%2};" : "=l"(r) : "f"(lo), "f"(hi)); return r;
}
__device__ __forceinline__ void upk2(ull v, float& lo, float& hi){
  asm("mov.b64 {%0,%1}, %2;" : "=f"(lo), "=f"(hi) : "l"(v));
}
__device__ __forceinline__ ull fma2(ull a, ull b, ull c){
  ull d; asm("fma.rn.f32x2 %0, %1, %2, %3;" : "=l"(d) : "l"(a), "l"(b), "l"(c)); return d;
}

// ------------------------- caption row l2norm -------------------------------
__global__ void k_capnorm(const float* __restrict__ cap){
  int row = blockIdx.x; int tid = threadIdx.x; // 128
  const float4* src = (const float4*)(cap + (size_t)row*CD);
  float4 v = src[tid];
  float ss = v.x*v.x + v.y*v.y + v.z*v.z + v.w*v.w;
  ss = warpSum(ss);
  __shared__ float rs[4]; __shared__ float s_inv;
  if ((tid&31)==0) rs[tid>>5] = ss;
  __syncthreads();
  if (tid==0){ float s = rs[0]+rs[1]+rs[2]+rs[3]; s_inv = 1.0f/fmaxf(sqrtf(s), 1e-12f); }
  __syncthreads();
  float inv = s_inv;
  ((float4*)(g_capn + (size_t)row*CD))[tid] = make_float4(v.x*inv, v.y*inv, v.z*inv, v.w*inv);
}

// ------------------------- spatial row l2norm -------------------------------
__global__ void k_spnorm(const float* __restrict__ img){
  int row = blockIdx.x; int b = row / NT, n = row % NT;
  int tid = threadIdx.x; // 128
  const float4* src = (const float4*)(img + ((size_t)(b*(NT+1) + 1 + n))*CD);
  float4 v = src[tid];
  float ss = v.x*v.x + v.y*v.y + v.z*v.z + v.w*v.w;
  ss = warpSum(ss);
  __shared__ float rs[4]; __shared__ float s_inv;
  if ((tid&31)==0) rs[tid>>5] = ss;
  __syncthreads();
  if (tid==0){ float s = rs[0]+rs[1]+rs[2]+rs[3]; s_inv = 1.0f/fmaxf(sqrtf(s), 1e-12f); }
  __syncthreads();
  float inv = s_inv;
  ((float4*)(g_spn + (size_t)row*CD))[tid] = make_float4(v.x*inv, v.y*inv, v.z*inv, v.w*inv);
}

// ------------- glo = l2norm(mean over tokens); s_im = glo . spn --------------
__global__ void k_glosim(const float* __restrict__ img){
  int b = blockIdx.x; int tid = threadIdx.x; // 256
  __shared__ float sg[CD];
  __shared__ float rs[8]; __shared__ float s_inv;
  float a0 = 0.f, a1 = 0.f;
  for (int n = 0; n < NT; n++){
    const float* r = img + ((size_t)(b*(NT+1) + 1 + n))*CD;
    a0 += r[tid]; a1 += r[tid+256];
  }
  a0 *= (1.0f/NT); a1 *= (1.0f/NT);
  float ss = a0*a0 + a1*a1;
  ss = warpSum(ss);
  if ((tid&31)==0) rs[tid>>5] = ss;
  __syncthreads();
  if (tid==0){ float s=0.f; for (int i=0;i<8;i++) s += rs[i]; s_inv = 1.0f/fmaxf(sqrtf(s),1e-12f); }
  __syncthreads();
  float inv = s_inv;
  sg[tid]       = a0*inv;
  sg[tid + 256] = a1*inv;
  __syncthreads();
  int wid = tid >> 5, lane = tid & 31;
  const float4* g4 = (const float4*)sg;
  for (int n = wid; n < NT; n += 8){
    const float4* sp = (const float4*)(g_spn + ((size_t)(b*NT + n))*CD);
    float d = 0.f;
    #pragma unroll
    for (int i=0;i<4;i++){
      float4 a = sp[lane + i*32]; float4 c = g4[lane + i*32];
      d += a.x*c.x + a.y*c.y + a.z*c.z + a.w*c.w;
    }
    d = warpSum(d);
    if (lane==0) g_sim[b*NT + n] = d;
  }
}

// ---------------- per-token LN stats (mu, rstd) over 9408 rows ---------------
__global__ void k_stats(const float* __restrict__ img){
  int wid = threadIdx.x >> 5, lane = threadIdx.x & 31;
  int row = blockIdx.x*8 + wid;
  int b = row / NT, n = row % NT;
  const float4* p = (const float4*)(img + ((size_t)(b*(NT+1) + 1 + n))*CD);
  float s = 0.f, ss = 0.f;
  #pragma unroll
  for (int i=0;i<4;i++){
    float4 x = p[lane + i*32];
    s  += x.x + x.y + x.z + x.w;
    ss += x.x*x.x + x.y*x.y + x.z*x.z + x.w*x.w;
  }
  s = warpSum(s); ss = warpSum(ss);
  if (lane==0){
    float mu = s * (1.0f/CD);
    float var = ss * (1.0f/CD) - mu*mu;
    g_tmu[row]   = mu;
    g_trstd[row] = rsqrtf(var + 1e-5f);
  }
}

// -------- GEMM1 (per-token): H = gelu( LN(tok) @ w1 + b1 ), 9408 x 102 ------
__global__ void k_mlp1(const float* __restrict__ img,
                       const float* __restrict__ lng, const float* __restrict__ lnb,
                       const float* __restrict__ w1,  const float* __restrict__ b1){
  __shared__ __align__(16) float As[32][68];
  __shared__ __align__(16) float Bs[32][68];
  __shared__ int   sIdx[64];
  __shared__ float sMu[64], sRstd[64];
  int rt = blockIdx.x * 64;
  int colTile = blockIdx.y * 64;
  int tid = threadIdx.x;
  if (tid < 64){
    int row = rt + tid;
    int b = row / NT, n = row % NT;
    sIdx[tid] = b*(NT+1) + 1 + n;
    sMu[tid] = g_tmu[row]; sRstd[tid] = g_trstd[row];
  }
  __syncthreads();
  ull acc[4][2];
  #pragma unroll
  for (int i=0;i<4;i++){ acc[i][0]=0ull; acc[i][1]=0ull; }
  int ty = tid >> 4, tx = tid & 15;
  for (int kt = 0; kt < CD; kt += 32){
    #pragma unroll
    for (int i=0;i<8;i++){
      int f = i*256 + tid;
      int r = f >> 5, c = f & 31;
      float v = img[(size_t)sIdx[r]*CD + kt + c];
      As[c][r] = (v - sMu[r]) * sRstd[r] * __ldg(&lng[kt+c]) + __ldg(&lnb[kt+c]);
    }
    #pragma unroll
    for (int i=0;i<8;i++){
      int f = i*256 + tid;
      int kk = f >> 6, nn = f & 63;
      int col = colTile + nn;
      Bs[kk][nn] = (col < HIDN) ? w1[(size_t)(kt+kk)*HIDN + col] : 0.f;
    }
    __syncthreads();
    #pragma unroll
    for (int kk=0; kk<32; kk++){
      float4 a = *(const float4*)&As[kk][ty<<2];
      const ull* bp = (const ull*)&Bs[kk][tx<<2];
      ull B0 = bp[0], B1 = bp[1];
      ull A0 = pk2(a.x,a.x), A1 = pk2(a.y,a.y), A2 = pk2(a.z,a.z), A3 = pk2(a.w,a.w);
      acc[0][0]=fma2(A0,B0,acc[0][0]); acc[0][1]=fma2(A0,B1,acc[0][1]);
      acc[1][0]=fma2(A1,B0,acc[1][0]); acc[1][1]=fma2(A1,B1,acc[1][1]);
      acc[2][0]=fma2(A2,B0,acc[2][0]); acc[2][1]=fma2(A2,B1,acc[2][1]);
      acc[3][0]=fma2(A3,B0,acc[3][0]); acc[3][1]=fma2(A3,B1,acc[3][1]);
    }
    __syncthreads();
  }
  #pragma unroll
  for (int i=0;i<4;i++){
    int row = rt + (ty<<2) + i;
    #pragma unroll
    for (int h=0;h<2;h++){
      float lo, hi; upk2(acc[i][h], lo, hi);
      float vv[2] = {lo, hi};
      #pragma unroll
      for (int q=0;q<2;q++){
        int col = colTile + (tx<<2) + h*2 + q;
        if (col < HIDN){
          float x = vv[q] + __ldg(&b1[col]);
          float gl = 0.5f * x * (1.0f + erff(x * 0.70710678118654752f));
          g_h[(size_t)row*HIDN + col] = gl;
        }
      }
    }
  }
}

// ------------- GEMM2 (per-token): tlog = H @ w2 + b2, 9408 x 39 --------------
__global__ void k_mlp2(const float* __restrict__ w2, const float* __restrict__ b2){
  __shared__ float Hs[64][104];
  __shared__ __align__(16) float w2s[HIDN][40];
  int rt = blockIdx.x * 64;
  int tid = threadIdx.x;
  for (int f = tid; f < 64*HIDN; f += 256){
    int r = f / HIDN, c = f - r*HIDN;
    Hs[r][c] = g_h[(size_t)rt*HIDN + f];
  }
  for (int f = tid; f < HIDN*NSEL; f += 256){
    int h = f / NSEL, t = f - h*NSEL;
    w2s[h][t] = w2[f];
  }
  for (int f = tid; f < HIDN; f += 256) w2s[f][39] = 0.f;
  __syncthreads();
  int r = tid >> 2, g = tid & 3;
  ull acc[5] = {0ull,0ull,0ull,0ull,0ull};
  for (int c = 0; c < HIDN; c++){
    float h = Hs[r][c];
    ull H = pk2(h,h);
    const ull* wp = (const ull*)&w2s[c][0];
    #pragma unroll
    for (int u=0;u<5;u++) acc[u] = fma2(H, wp[g + 4*u], acc[u]);
  }
  #pragma unroll
  for (int u=0;u<5;u++){
    float lo, hi; upk2(acc[u], lo, hi);
    int t0 = 2*(g + 4*u);
    g_tlog[(size_t)(rt + r)*NSEL + t0] = lo + __ldg(&b2[t0]);
    if (t0 + 1 < NSEL)
      g_tlog[(size_t)(rt + r)*NSEL + t0 + 1] = hi + __ldg(&b2[t0+1]);
  }
}

// ---- score v6: 256 thr, k-pair fma2; warps split tokens, single tiles -------
// warp w: wg = w>>1 owns caption rows {wg+4i}, wh = w&1 owns token half.
__global__ void __launch_bounds__(256) k_score(){
  __shared__ __align__(16) ull As2[16][34];
  __shared__ __align__(16) ull Bs2[16][201];
  __shared__ float red[4][196];
  int jb = blockIdx.x; int j = jb / BV, b = jb % BV;
  int tid = threadIdx.x;
  int w = tid >> 5, lane = tid & 31;
  int wg = w >> 1, wh = w & 1;
  int tbase = wh * 98;
  ull acc[8][3], accT[8];
  #pragma unroll
  for (int i=0;i<8;i++){
    acc[i][0]=0ull; acc[i][1]=0ull; acc[i][2]=0ull; accT[i]=0ull;
  }
  for (int kt = 0; kt < CD; kt += 32){
    {
      int m = tid >> 3;              // 0..31
      int q = tid & 7;               // 0..7
      float4 v = *(const float4*)&g_capn[((size_t)(j*MW + m))*CD + kt + q*4];
      As2[2*q]  [m] = pk2(v.x, v.y);
      As2[2*q+1][m] = pk2(v.z, v.w);
    }
    for (int f = tid; f < NT*8; f += 256){
      int t = f >> 3, q = f & 7;
      float4 v = *(const float4*)&g_spn[((size_t)(b*NT + t))*CD + kt + q*4];
      Bs2[2*q]  [t] = pk2(v.x, v.y);
      Bs2[2*q+1][t] = pk2(v.z, v.w);
    }
    __syncthreads();
    #pragma unroll
    for (int kk2=0; kk2<16; kk2++){
      ull a[8];
      #pragma unroll
      for (int i=0;i<8;i++) a[i] = As2[kk2][wg + 4*i];
      const ull* brow = &Bs2[kk2][tbase];
      #pragma unroll
      for (int v=0;v<3;v++){
        ull B = brow[lane + 32*v];
        #pragma unroll
        for (int i=0;i<8;i++) acc[i][v] = fma2(a[i], B, acc[i][v]);
      }
      if (lane < 2){
        ull B = brow[96 + lane];
        #pragma unroll
        for (int i=0;i<8;i++) accT[i] = fma2(a[i], B, accT[i]);
      }
    }
    __syncthreads();
  }
  #pragma unroll
  for (int v=0;v<3;v++){
    float mx = -3.4e38f;
    #pragma unroll
    for (int i=0;i<8;i++){
      float lo, hi; upk2(acc[i][v], lo, hi);
      mx = fmaxf(mx, lo + hi);
    }
    red[wg][tbase + lane + 32*v] = mx;
  }
  if (lane < 2){
    float mx = -3.4e38f;
    #pragma unroll
    for (int i=0;i<8;i++){
      float lo, hi; upk2(accT[i], lo, hi);
      mx = fmaxf(mx, lo + hi);
    }
    red[wg][tbase + 96 + lane] = mx;
  }
  __syncthreads();
  if (tid < NT){
    float mx = fmaxf(fmaxf(red[0][tid], red[1][tid]), fmaxf(red[2][tid], red[3][tid]));
    g_score[(size_t)jb*NT + tid] = g_sim[b*NT + tid] + mx;
  }
}

// ---- per (j,b): hybrid bitonic sort + extra token + fused softmax -----------
__global__ void k_sort(const float* __restrict__ img, const float* __restrict__ scale){
  __shared__ float svals[256];
  __shared__ int   sidxs[256];
  __shared__ float wbuf[NKEEP];
  __shared__ float rs[8]; __shared__ float s_tot;
  __shared__ float s[NKEEP][40];
  int jb = blockIdx.x; int b = jb % BV;
  int tid = threadIdx.x;
  int w = tid >> 5, lane = tid & 31;
  float v = (tid < NT) ? -g_score[(size_t)jb*NT + tid] : 3.4e38f;
  int id = tid;
  const unsigned FULL = 0xffffffffu;
  for (int k = 2; k <= 256; k <<= 1){
    for (int sdist = k >> 1; sdist > 0; sdist >>= 1){
      bool up = ((tid & k) == 0);
      bool lower = ((tid & sdist) == 0);
      if (sdist >= 32){
        svals[tid] = v; sidxs[tid] = id;
        __syncthreads();
        int p = tid ^ sdist;
        float ov = svals[p]; int oi = sidxs[p];
        bool swap = lower ? ((v > ov) == up) : ((ov > v) == up);
        if (swap){ v = ov; id = oi; }
        __syncthreads();
      } else {
        float ov = __shfl_xor_sync(FULL, v, sdist);
        int oi   = __shfl_xor_sync(FULL, id, sdist);
        bool swap = lower ? ((v > ov) == up) : ((ov > v) == up);
        if (swap){ v = ov; id = oi; }
      }
    }
  }
  svals[tid] = v; sidxs[tid] = id;
  __syncthreads();
  if (tid < NKEEP) g_keep[(size_t)jb*NKEEP + tid] = sidxs[tid];
  float e = 0.f;
  if (tid < NKEEP){ e = expf(svals[NKEEP] - svals[NKEEP + tid]); wbuf[tid] = e; }
  float vv = warpSum(e);
  if ((tid&31)==0) rs[tid>>5] = vv;
  __syncthreads();
  if (tid==0){ float ssum=0.f; for (int i=0;i<8;i++) ssum += rs[i]; s_tot = ssum; }
  __syncthreads();
  float invq = 1.0f / s_tot;
  {
    float a0 = 0.f, a1 = 0.f;
    for (int i = 0; i < NKEEP; i++){
      float wq = wbuf[i];
      const float* r = img + ((size_t)(b*(NT+1) + 1 + sidxs[NKEEP+i]))*CD;
      a0 += wq * r[tid]; a1 += wq * r[tid+256];
    }
    g_extra[(size_t)jb*CD + tid]       = a0*invq;
    g_extra[(size_t)jb*CD + tid + 256] = a1*invq;
  }
  // ---- fused softmax over keep-gathered logits ----
  float sc = __ldg(scale);
  for (int f = tid; f < NKEEP*NSEL; f += 256){
    int k = f / NSEL, t = f - k*NSEL;
    s[k][t] = g_tlog[(size_t)(b*NT + sidxs[k])*NSEL + t] * sc;
  }
  __syncthreads();
  for (int t = w; t < NSEL; t += 8){
    float v0 = s[lane][t], v1 = s[lane+32][t], v2 = s[lane+64][t];
    float v3 = (lane < 2) ? s[lane+96][t] : -3.4e38f;
    float mx = warpMax(fmaxf(fmaxf(v0,v1), fmaxf(v2,v3)));
    float e0 = expf(v0-mx), e1 = expf(v1-mx), e2 = expf(v2-mx);
    float e3 = (lane < 2) ? expf(v3-mx) : 0.f;
    float tot = warpSum(e0+e1+e2+e3);
    float inv2 = 1.0f / tot;
    s[lane][t] = e0*inv2; s[lane+32][t] = e1*inv2; s[lane+64][t] = e2*inv2;
    if (lane < 2) s[lane+96][t] = e3*inv2;
  }
  __syncthreads();
  for (int f = tid; f < NKEEP*NSEL; f += 256){
    int k = f / NSEL, t = f - k*NSEL;
    g_wt[(size_t)jb*NKEEP*NSEL + f] = s[k][t];
  }
}

// ------- aggregation tiled GEMM: toks[t][c] = sum_k wtt[k][t]*sel[k][c] ------
__global__ void __launch_bounds__(128) k_aggr(const float* __restrict__ img){
  __shared__ __align__(16) ull   wdup[128][40];
  __shared__ __align__(16) float Bs[32][132];
  __shared__ int keeps[128];
  int jb = blockIdx.x; int b = jb % BV;
  int ctile = blockIdx.y * 128;
  int tid = threadIdx.x;    // 128
  for (int f = tid; f < NKEEP*NSEL; f += 128){
    int k = f / NSEL, t = f - k*NSEL;
    float w = g_wt[(size_t)jb*NKEEP*NSEL + f];
    wdup[k][t] = pk2(w, w);
  }
  wdup[tid][39] = 0ull;
  for (int f = tid; f < 30*40; f += 128){
    int k = NKEEP + f/40, t = f%40;
    wdup[k][t] = 0ull;
  }
  keeps[tid] = g_keep[(size_t)jb*NKEEP + ((tid < NKEEP) ? tid : 0)];
  __syncthreads();
  int colLane = tid & 15;
  int tg = tid >> 4;          // 0..7 token groups (5 t each)
  ull acc[5][4];
  #pragma unroll
  for (int i=0;i<5;i++)
    #pragma unroll
    for (int u=0;u<4;u++) acc[i][u] = 0ull;
  for (int kt = 0; kt < 128; kt += 32){
    #pragma unroll
    for (int i=0;i<8;i++){
      int f = i*128 + tid;
      int r = f >> 5, c4 = f & 31;
      float4 v = *(const float4*)&img[((size_t)(b*(NT+1) + 1 + keeps[kt + r]))*CD + ctile + c4*4];
      *(float4*)&Bs[r][c4*4] = v;
    }
    __syncthreads();
    #pragma unroll
    for (int kk=0; kk<32; kk++){
      const ull* bp = (const ull*)&Bs[kk][0];
      ull B0 = bp[colLane], B1 = bp[colLane+16], B2 = bp[colLane+32], B3 = bp[colLane+48];
      const ull* wr = &wdup[kt+kk][tg*5];
      #pragma unroll
      for (int i=0;i<5;i++){
        ull W = wr[i];
        acc[i][0] = fma2(W, B0, acc[i][0]);
        acc[i][1] = fma2(W, B1, acc[i][1]);
        acc[i][2] = fma2(W, B2, acc[i][2]);
        acc[i][3] = fma2(W, B3, acc[i][3]);
      }
    }
    __syncthreads();
  }
  #pragma unroll
  for (int i=0;i<5;i++){
    int t = tg*5 + i;
    if (t < NSEL){
      #pragma unroll
      for (int u=0;u<4;u++){
        float lo, hi; upk2(acc[i][u], lo, hi);
        *(float2*)&g_toks[((size_t)jb*NTOKS + 1 + t)*CD + ctile + 2*(colLane + 16*u)]
            = make_float2(lo, hi);
      }
    }
  }
  {
    int c = ctile + tid;
    g_toks[((size_t)jb*NTOKS + 0)*CD + c]  = img[((size_t)(b*(NT+1)))*CD + c];
    g_toks[((size_t)jb*NTOKS + 40)*CD + c] = g_extra[(size_t)jb*CD + c];
  }
}

// ----- c2t v2: k-pair packed GEMM + fused token-norms + leaky + reductions ---
__global__ void __launch_bounds__(128) k_c2t(float* __restrict__ out){
  __shared__ __align__(16) ull As2[16][34];
  __shared__ __align__(16) ull Bs2[16][42];
  __shared__ float c2t[MW][48];
  __shared__ float inv[48];
  __shared__ float sqarr[NTOKS][8];
  __shared__ float redA[MW], redB[NTOKS];
  int jb = blockIdx.x; int j = jb / BV, b = jb % BV;
  int tid = threadIdx.x;
  int w = tid >> 5, lane = tid & 31;
  ull acc0[8], acc1[8];
  #pragma unroll
  for (int i=0;i<8;i++){ acc0[i]=0ull; acc1[i]=0ull; }
  float sq0 = 0.f, sq1 = 0.f, sq2 = 0.f;
  for (int kt = 0; kt < CD; kt += 32){
    {
      int m = tid >> 2;
      #pragma unroll
      for (int h=0;h<2;h++){
        int q = (tid & 3) + 4*h;
        float4 v = *(const float4*)&g_capn[((size_t)(j*MW + m))*CD + kt + q*4];
        As2[2*q]  [m] = pk2(v.x, v.y);
        As2[2*q+1][m] = pk2(v.z, v.w);
      }
    }
    #pragma unroll
    for (int it=0; it<3; it++){
      int f = it*128 + tid;
      if (f < NTOKS*8){
        int t = f >> 3, q = f & 7;
        float4 v = *(const float4*)&g_toks[((size_t)jb*NTOKS + t)*CD + kt + q*4];
        Bs2[2*q]  [t] = pk2(v.x, v.y);
        Bs2[2*q+1][t] = pk2(v.z, v.w);
        float p = v.x*v.x + v.y*v.y + v.z*v.z + v.w*v.w;
        if (it==0) sq0 += p; else if (it==1) sq1 += p; else sq2 += p;
      }
    }
    __syncthreads();
    #pragma unroll
    for (int kk2=0; kk2<16; kk2++){
      ull a[8];
      #pragma unroll
      for (int i=0;i<8;i++) a[i] = As2[kk2][w + 4*i];
      ull B0 = Bs2[kk2][lane];
      #pragma unroll
      for (int i=0;i<8;i++) acc0[i] = fma2(a[i], B0, acc0[i]);
      if (lane < 9){
        ull B1 = Bs2[kk2][32 + lane];
        #pragma unroll
        for (int i=0;i<8;i++) acc1[i] = fma2(a[i], B1, acc1[i]);
      }
    }
    __syncthreads();
  }
  sqarr[tid>>3][tid&7] = sq0;
  {
    int f1 = 128 + tid;
    sqarr[f1>>3][f1&7] = sq1;
    int f2 = 256 + tid;
    if (f2 < NTOKS*8) sqarr[f2>>3][f2&7] = sq2;
  }
  __syncthreads();
  if (tid < 48){
    if (tid < NTOKS){
      float s = 0.f;
      #pragma unroll
      for (int q=0;q<8;q++) s += sqarr[tid][q];
      inv[tid] = 1.0f / fmaxf(sqrtf(s), 1e-12f);
    } else inv[tid] = 0.f;
  }
  __syncthreads();
  {
    float iv0 = inv[lane];
    float iv1 = (lane < 9) ? inv[32 + lane] : 0.f;
    #pragma unroll
    for (int i=0;i<8;i++){
      int row = w + 4*i;
      float lo, hi; upk2(acc0[i], lo, hi);
      float v0 = (lo + hi) * iv0;
      c2t[row][lane] = (v0 >= 0.f) ? v0 : 0.1f*v0;
      if (lane < 9){
        upk2(acc1[i], lo, hi);
        float v1 = (lo + hi) * iv1;
        c2t[row][32 + lane] = (v1 >= 0.f) ? v1 : 0.1f*v1;
      }
    }
  }
  __syncthreads();
  if (tid < MW){
    float mx = -3.4e38f;
    for (int t=0;t<NTOKS;t++) mx = fmaxf(mx, c2t[tid][t]);
    redA[tid] = mx;
  }
  if (tid < NTOKS){
    float mx = -3.4e38f;
    for (int m=0;m<MW;m++) mx = fmaxf(mx, c2t[m][tid]);
    redB[tid] = mx;
  }
  __syncthreads();
  if (tid == 0){
    float row = 0.f; for (int m=0;m<MW;m++) row += redA[m];
    row *= (1.0f/MW);
    float col = 0.f; for (int t=0;t<NTOKS;t++) col += redB[t];
    col *= (1.0f/NTOKS);
    out[b*BT + j] = row + col;
  }
}

// ----------------------------- launcher --------------------------------------
extern "C" void kernel_launch(void* const* d_in, const int* in_sizes, int n_in,
                              void* d_out, int out_size){
  const float* img   = (const float*)d_in[0];
  const float* cap   = (const float*)d_in[1];
  const float* lng   = (const float*)d_in[3];
  const float* lnb   = (const float*)d_in[4];
  const float* w1    = (const float*)d_in[5];
  const float* b1    = (const float*)d_in[6];
  const float* w2    = (const float*)d_in[7];
  const float* b2    = (const float*)d_in[8];
  const float* scale = (const float*)d_in[9];
  float* out = (float*)d_out;

  k_capnorm<<<BT*MW, 128>>>(cap);
  k_spnorm<<<BV*NT, 128>>>(img);
  k_glosim<<<BV, 256>>>(img);
  k_stats<<<NTOK/8, 256>>>(img);
  k_mlp1<<<dim3(NTOK/64, 2), 256>>>(img, lng, lnb, w1, b1);
  k_mlp2<<<NTOK/64, 256>>>(w2, b2);
  k_score<<<NPAIR, 256>>>();
  k_sort<<<NPAIR, 256>>>(img, scale);
  k_aggr<<<dim3(NPAIR, 4), 128>>>(img);
  k_c2t<<<NPAIR, 128>>>(out);
}

// round 15
// speedup vs baseline: 1.4614x; 1.4614x over previous
#include <cuda_runtime.h>
#include <math.h>

#define BV 48
#define BT 48
#define MW 32
#define NT 196
#define CD 512
#define HIDN 102
#define NKEEP 98
#define NSEL 39
#define NTOKS 41
#define NPAIR (BT*BV)
#define NTOK (BV*NT)

typedef unsigned long long ull;

// ---------------- scratch (device globals) ----------------------------------
__device__ float g_capn[BT*MW*CD];
__device__ float g_spn[BV*NT*CD];
__device__ float g_sim[BV*NT];
__device__ float g_score[NPAIR*NT];
__device__ int   g_keep[NPAIR*NKEEP];
__device__ float g_extra[NPAIR*CD];
__device__ float g_tmu[NTOK];
__device__ float g_trstd[NTOK];
__device__ float g_h[(size_t)NTOK*HIDN];
__device__ float g_tlog[(size_t)NTOK*NSEL];
__device__ float g_wt[(size_t)NPAIR*NKEEP*NSEL];
__device__ float g_toks[(size_t)NPAIR*NTOKS*CD];

__device__ __forceinline__ float warpSum(float v){
  #pragma unroll
  for (int o=16;o;o>>=1) v += __shfl_xor_sync(0xffffffffu, v, o);
  return v;
}
__device__ __forceinline__ float warpMax(float v){
  #pragma unroll
  for (int o=16;o;o>>=1) v = fmaxf(v, __shfl_xor_sync(0xffffffffu, v, o));
  return v;
}
__device__ __forceinline__ ull pk2(float lo, float hi){
  ull r; asm("mov.b64 %0, {%1,%2};" : "=l"(r) : "f"(lo), "f"(hi)); return r;
}
__device__ __forceinline__ void upk2(ull v, float& lo, float& hi){
  asm("mov.b64 {%0,%1}, %2;" : "=f"(lo), "=f"(hi) : "l"(v));
}
__device__ __forceinline__ ull fma2(ull a, ull b, ull c){
  ull d; asm("fma.rn.f32x2 %0, %1, %2, %3;" : "=l"(d) : "l"(a), "l"(b), "l"(c)); return d;
}

// ------------------------- caption row l2norm -------------------------------
__global__ void k_capnorm(const float* __restrict__ cap){
  int row = blockIdx.x; int tid = threadIdx.x; // 128
  const float4* src = (const float4*)(cap + (size_t)row*CD);
  float4 v = src[tid];
  float ss = v.x*v.x + v.y*v.y + v.z*v.z + v.w*v.w;
  ss = warpSum(ss);
  __shared__ float rs[4]; __shared__ float s_inv;
  if ((tid&31)==0) rs[tid>>5] = ss;
  __syncthreads();
  if (tid==0){ float s = rs[0]+rs[1]+rs[2]+rs[3]; s_inv = 1.0f/fmaxf(sqrtf(s), 1e-12f); }
  __syncthreads();
  float inv = s_inv;
  ((float4*)(g_capn + (size_t)row*CD))[tid] = make_float4(v.x*inv, v.y*inv, v.z*inv, v.w*inv);
}

// ------------------------- spatial row l2norm -------------------------------
__global__ void k_spnorm(const float* __restrict__ img){
  int row = blockIdx.x; int b = row / NT, n = row % NT;
  int tid = threadIdx.x; // 128
  const float4* src = (const float4*)(img + ((size_t)(b*(NT+1) + 1 + n))*CD);
  float4 v = src[tid];
  float ss = v.x*v.x + v.y*v.y + v.z*v.z + v.w*v.w;
  ss = warpSum(ss);
  __shared__ float rs[4]; __shared__ float s_inv;
  if ((tid&31)==0) rs[tid>>5] = ss;
  __syncthreads();
  if (tid==0){ float s = rs[0]+rs[1]+rs[2]+rs[3]; s_inv = 1.0f/fmaxf(sqrtf(s), 1e-12f); }
  __syncthreads();
  float inv = s_inv;
  ((float4*)(g_spn + (size_t)row*CD))[tid] = make_float4(v.x*inv, v.y*inv, v.z*inv, v.w*inv);
}

// ------------- glo = l2norm(mean over tokens); s_im = glo . spn --------------
__global__ void k_glosim(const float* __restrict__ img){
  int b = blockIdx.x; int tid = threadIdx.x; // 256
  __shared__ float sg[CD];
  __shared__ float rs[8]; __shared__ float s_inv;
  float a0 = 0.f, a1 = 0.f;
  for (int n = 0; n < NT; n++){
    const float* r = img + ((size_t)(b*(NT+1) + 1 + n))*CD;
    a0 += r[tid]; a1 += r[tid+256];
  }
  a0 *= (1.0f/NT); a1 *= (1.0f/NT);
  float ss = a0*a0 + a1*a1;
  ss = warpSum(ss);
  if ((tid&31)==0) rs[tid>>5] = ss;
  __syncthreads();
  if (tid==0){ float s=0.f; for (int i=0;i<8;i++) s += rs[i]; s_inv = 1.0f/fmaxf(sqrtf(s),1e-12f); }
  __syncthreads();
  float inv = s_inv;
  sg[tid]       = a0*inv;
  sg[tid + 256] = a1*inv;
  __syncthreads();
  int wid = tid >> 5, lane = tid & 31;
  const float4* g4 = (const float4*)sg;
  for (int n = wid; n < NT; n += 8){
    const float4* sp = (const float4*)(g_spn + ((size_t)(b*NT + n))*CD);
    float d = 0.f;
    #pragma unroll
    for (int i=0;i<4;i++){
      float4 a = sp[lane + i*32]; float4 c = g4[lane + i*32];
      d += a.x*c.x + a.y*c.y + a.z*c.z + a.w*c.w;
    }
    d = warpSum(d);
    if (lane==0) g_sim[b*NT + n] = d;
  }
}

// ---------------- per-token LN stats (mu, rstd) over 9408 rows ---------------
__global__ void k_stats(const float* __restrict__ img){
  int wid = threadIdx.x >> 5, lane = threadIdx.x & 31;
  int row = blockIdx.x*8 + wid;
  int b = row / NT, n = row % NT;
  const float4* p = (const float4*)(img + ((size_t)(b*(NT+1) + 1 + n))*CD);
  float s = 0.f, ss = 0.f;
  #pragma unroll
  for (int i=0;i<4;i++){
    float4 x = p[lane + i*32];
    s  += x.x + x.y + x.z + x.w;
    ss += x.x*x.x + x.y*x.y + x.z*x.z + x.w*x.w;
  }
  s = warpSum(s); ss = warpSum(ss);
  if (lane==0){
    float mu = s * (1.0f/CD);
    float var = ss * (1.0f/CD) - mu*mu;
    g_tmu[row]   = mu;
    g_trstd[row] = rsqrtf(var + 1e-5f);
  }
}

// -------- GEMM1 (per-token): H = gelu( LN(tok) @ w1 + b1 ), 9408 x 102 ------
__global__ void k_mlp1(const float* __restrict__ img,
                       const float* __restrict__ lng, const float* __restrict__ lnb,
                       const float* __restrict__ w1,  const float* __restrict__ b1){
  __shared__ __align__(16) float As[32][68];
  __shared__ __align__(16) float Bs[32][68];
  __shared__ int   sIdx[64];
  __shared__ float sMu[64], sRstd[64];
  int rt = blockIdx.x * 64;
  int colTile = blockIdx.y * 64;
  int tid = threadIdx.x;
  if (tid < 64){
    int row = rt + tid;
    int b = row / NT, n = row % NT;
    sIdx[tid] = b*(NT+1) + 1 + n;
    sMu[tid] = g_tmu[row]; sRstd[tid] = g_trstd[row];
  }
  __syncthreads();
  ull acc[4][2];
  #pragma unroll
  for (int i=0;i<4;i++){ acc[i][0]=0ull; acc[i][1]=0ull; }
  int ty = tid >> 4, tx = tid & 15;
  for (int kt = 0; kt < CD; kt += 32){
    #pragma unroll
    for (int i=0;i<8;i++){
      int f = i*256 + tid;
      int r = f >> 5, c = f & 31;
      float v = img[(size_t)sIdx[r]*CD + kt + c];
      As[c][r] = (v - sMu[r]) * sRstd[r] * __ldg(&lng[kt+c]) + __ldg(&lnb[kt+c]);
    }
    #pragma unroll
    for (int i=0;i<8;i++){
      int f = i*256 + tid;
      int kk = f >> 6, nn = f & 63;
      int col = colTile + nn;
      Bs[kk][nn] = (col < HIDN) ? w1[(size_t)(kt+kk)*HIDN + col] : 0.f;
    }
    __syncthreads();
    #pragma unroll
    for (int kk=0; kk<32; kk++){
      float4 a = *(const float4*)&As[kk][ty<<2];
      const ull* bp = (const ull*)&Bs[kk][tx<<2];
      ull B0 = bp[0], B1 = bp[1];
      ull A0 = pk2(a.x,a.x), A1 = pk2(a.y,a.y), A2 = pk2(a.z,a.z), A3 = pk2(a.w,a.w);
      acc[0][0]=fma2(A0,B0,acc[0][0]); acc[0][1]=fma2(A0,B1,acc[0][1]);
      acc[1][0]=fma2(A1,B0,acc[1][0]); acc[1][1]=fma2(A1,B1,acc[1][1]);
      acc[2][0]=fma2(A2,B0,acc[2][0]); acc[2][1]=fma2(A2,B1,acc[2][1]);
      acc[3][0]=fma2(A3,B0,acc[3][0]); acc[3][1]=fma2(A3,B1,acc[3][1]);
    }
    __syncthreads();
  }
  #pragma unroll
  for (int i=0;i<4;i++){
    int row = rt + (ty<<2) + i;
    #pragma unroll
    for (int h=0;h<2;h++){
      float lo, hi; upk2(acc[i][h], lo, hi);
      float vv[2] = {lo, hi};
      #pragma unroll
      for (int q=0;q<2;q++){
        int col = colTile + (tx<<2) + h*2 + q;
        if (col < HIDN){
          float x = vv[q] + __ldg(&b1[col]);
          float gl = 0.5f * x * (1.0f + erff(x * 0.70710678118654752f));
          g_h[(size_t)row*HIDN + col] = gl;
        }
      }
    }
  }
}

// ------------- GEMM2 (per-token): tlog = H @ w2 + b2, 9408 x 39 --------------
__global__ void k_mlp2(const float* __restrict__ w2, const float* __restrict__ b2){
  __shared__ float Hs[64][104];
  __shared__ __align__(16) float w2s[HIDN][40];
  int rt = blockIdx.x * 64;
  int tid = threadIdx.x;
  for (int f = tid; f < 64*HIDN; f += 256){
    int r = f / HIDN, c = f - r*HIDN;
    Hs[r][c] = g_h[(size_t)rt*HIDN + f];
  }
  for (int f = tid; f < HIDN*NSEL; f += 256){
    int h = f / NSEL, t = f - h*NSEL;
    w2s[h][t] = w2[f];
  }
  for (int f = tid; f < HIDN; f += 256) w2s[f][39] = 0.f;
  __syncthreads();
  int r = tid >> 2, g = tid & 3;
  ull acc[5] = {0ull,0ull,0ull,0ull,0ull};
  for (int c = 0; c < HIDN; c++){
    float h = Hs[r][c];
    ull H = pk2(h,h);
    const ull* wp = (const ull*)&w2s[c][0];
    #pragma unroll
    for (int u=0;u<5;u++) acc[u] = fma2(H, wp[g + 4*u], acc[u]);
  }
  #pragma unroll
  for (int u=0;u<5;u++){
    float lo, hi; upk2(acc[u], lo, hi);
    int t0 = 2*(g + 4*u);
    g_tlog[(size_t)(rt + r)*NSEL + t0] = lo + __ldg(&b2[t0]);
    if (t0 + 1 < NSEL)
      g_tlog[(size_t)(rt + r)*NSEL + t0 + 1] = hi + __ldg(&b2[t0+1]);
  }
}

// ---- score v4 (R12 known-good): k-pair fma2, 128 threads --------------------
__global__ void __launch_bounds__(128) k_score(){
  __shared__ __align__(16) ull As2[16][34];
  __shared__ __align__(16) ull Bs2[16][201];
  __shared__ float red[4][196];
  int jb = blockIdx.x; int j = jb / BV, b = jb % BV;
  int tid = threadIdx.x;
  int w = tid >> 5, lane = tid & 31;
  ull acc[8][6], accT[8];
  #pragma unroll
  for (int i=0;i<8;i++){
    #pragma unroll
    for (int v=0;v<6;v++) acc[i][v] = 0ull;
    accT[i] = 0ull;
  }
  for (int kt = 0; kt < CD; kt += 32){
    {
      int m = tid >> 2;
      #pragma unroll
      for (int h=0;h<2;h++){
        int q = (tid & 3) + 4*h;
        float4 v = *(const float4*)&g_capn[((size_t)(j*MW + m))*CD + kt + q*4];
        As2[2*q]  [m] = pk2(v.x, v.y);
        As2[2*q+1][m] = pk2(v.z, v.w);
      }
    }
    for (int f = tid; f < NT*8; f += 128){
      int t = f >> 3, q = f & 7;
      float4 v = *(const float4*)&g_spn[((size_t)(b*NT + t))*CD + kt + q*4];
      Bs2[2*q]  [t] = pk2(v.x, v.y);
      Bs2[2*q+1][t] = pk2(v.z, v.w);
    }
    __syncthreads();
    #pragma unroll
    for (int kk2=0; kk2<16; kk2++){
      ull a[8];
      #pragma unroll
      for (int i=0;i<8;i++) a[i] = As2[kk2][w + 4*i];
      const ull* brow = &Bs2[kk2][0];
      #pragma unroll
      for (int v=0;v<6;v++){
        ull B = brow[lane + 32*v];
        #pragma unroll
        for (int i=0;i<8;i++) acc[i][v] = fma2(a[i], B, acc[i][v]);
      }
      if (lane < 4){
        ull B = brow[192 + lane];
        #pragma unroll
        for (int i=0;i<8;i++) accT[i] = fma2(a[i], B, accT[i]);
      }
    }
    __syncthreads();
  }
  #pragma unroll
  for (int v=0;v<6;v++){
    float mx = -3.4e38f;
    #pragma unroll
    for (int i=0;i<8;i++){
      float lo, hi; upk2(acc[i][v], lo, hi);
      mx = fmaxf(mx, lo + hi);
    }
    red[w][lane + 32*v] = mx;
  }
  if (lane < 4){
    float mx = -3.4e38f;
    #pragma unroll
    for (int i=0;i<8;i++){
      float lo, hi; upk2(accT[i], lo, hi);
      mx = fmaxf(mx, lo + hi);
    }
    red[w][192 + lane] = mx;
  }
  __syncthreads();
  for (int t = tid; t < NT; t += 128){
    float mx = fmaxf(fmaxf(red[0][t], red[1][t]), fmaxf(red[2][t], red[3][t]));
    g_score[(size_t)jb*NT + t] = g_sim[b*NT + t] + mx;
  }
}

// ---- per (j,b): hybrid bitonic sort + extra token + fused softmax -----------
__global__ void k_sort(const float* __restrict__ img, const float* __restrict__ scale){
  __shared__ float svals[256];
  __shared__ int   sidxs[256];
  __shared__ float wbuf[NKEEP];
  __shared__ float rs[8]; __shared__ float s_tot;
  __shared__ float s[NKEEP][40];
  int jb = blockIdx.x; int b = jb % BV;
  int tid = threadIdx.x;
  int w = tid >> 5, lane = tid & 31;
  float v = (tid < NT) ? -g_score[(size_t)jb*NT + tid] : 3.4e38f;
  int id = tid;
  const unsigned FULL = 0xffffffffu;
  for (int k = 2; k <= 256; k <<= 1){
    for (int sdist = k >> 1; sdist > 0; sdist >>= 1){
      bool up = ((tid & k) == 0);
      bool lower = ((tid & sdist) == 0);
      if (sdist >= 32){
        svals[tid] = v; sidxs[tid] = id;
        __syncthreads();
        int p = tid ^ sdist;
        float ov = svals[p]; int oi = sidxs[p];
        bool swap = lower ? ((v > ov) == up) : ((ov > v) == up);
        if (swap){ v = ov; id = oi; }
        __syncthreads();
      } else {
        float ov = __shfl_xor_sync(FULL, v, sdist);
        int oi   = __shfl_xor_sync(FULL, id, sdist);
        bool swap = lower ? ((v > ov) == up) : ((ov > v) == up);
        if (swap){ v = ov; id = oi; }
      }
    }
  }
  svals[tid] = v; sidxs[tid] = id;
  __syncthreads();
  if (tid < NKEEP) g_keep[(size_t)jb*NKEEP + tid] = sidxs[tid];
  float e = 0.f;
  if (tid < NKEEP){ e = expf(svals[NKEEP] - svals[NKEEP + tid]); wbuf[tid] = e; }
  float vv = warpSum(e);
  if ((tid&31)==0) rs[tid>>5] = vv;
  __syncthreads();
  if (tid==0){ float ssum=0.f; for (int i=0;i<8;i++) ssum += rs[i]; s_tot = ssum; }
  __syncthreads();
  float invq = 1.0f / s_tot;
  {
    float a0 = 0.f, a1 = 0.f;
    for (int i = 0; i < NKEEP; i++){
      float wq = wbuf[i];
      const float* r = img + ((size_t)(b*(NT+1) + 1 + sidxs[NKEEP+i]))*CD;
      a0 += wq * r[tid]; a1 += wq * r[tid+256];
    }
    g_extra[(size_t)jb*CD + tid]       = a0*invq;
    g_extra[(size_t)jb*CD + tid + 256] = a1*invq;
  }
  // ---- fused softmax over keep-gathered logits ----
  float sc = __ldg(scale);
  for (int f = tid; f < NKEEP*NSEL; f += 256){
    int k = f / NSEL, t = f - k*NSEL;
    s[k][t] = g_tlog[(size_t)(b*NT + sidxs[k])*NSEL + t] * sc;
  }
  __syncthreads();
  for (int t = w; t < NSEL; t += 8){
    float v0 = s[lane][t], v1 = s[lane+32][t], v2 = s[lane+64][t];
    float v3 = (lane < 2) ? s[lane+96][t] : -3.4e38f;
    float mx = warpMax(fmaxf(fmaxf(v0,v1), fmaxf(v2,v3)));
    float e0 = expf(v0-mx), e1 = expf(v1-mx), e2 = expf(v2-mx);
    float e3 = (lane < 2) ? expf(v3-mx) : 0.f;
    float tot = warpSum(e0+e1+e2+e3);
    float inv2 = 1.0f / tot;
    s[lane][t] = e0*inv2; s[lane+32][t] = e1*inv2; s[lane+64][t] = e2*inv2;
    if (lane < 2) s[lane+96][t] = e3*inv2;
  }
  __syncthreads();
  for (int f = tid; f < NKEEP*NSEL; f += 256){
    int k = f / NSEL, t = f - k*NSEL;
    g_wt[(size_t)jb*NKEEP*NSEL + f] = s[k][t];
  }
}

// ------- aggregation multi-tile: one block per pair, 4 column tiles ----------
__global__ void __launch_bounds__(128) k_aggr(const float* __restrict__ img){
  __shared__ __align__(16) ull   wdup[128][40];
  __shared__ __align__(16) float Bs[32][132];
  __shared__ int keeps[128];
  int jb = blockIdx.x; int b = jb % BV;
  int tid = threadIdx.x;    // 128
  for (int f = tid; f < NKEEP*NSEL; f += 128){
    int k = f / NSEL, t = f - k*NSEL;
    float w = g_wt[(size_t)jb*NKEEP*NSEL + f];
    wdup[k][t] = pk2(w, w);
  }
  wdup[tid][39] = 0ull;
  for (int f = tid; f < 30*40; f += 128){
    int k = NKEEP + f/40, t = f%40;
    wdup[k][t] = 0ull;
  }
  keeps[tid] = g_keep[(size_t)jb*NKEEP + ((tid < NKEEP) ? tid : 0)];
  __syncthreads();
  int colLane = tid & 15;
  int tg = tid >> 4;          // 0..7 token groups (5 t each)
  for (int ctile = 0; ctile < CD; ctile += 128){
    ull acc[5][4];
    #pragma unroll
    for (int i=0;i<5;i++)
      #pragma unroll
      for (int u=0;u<4;u++) acc[i][u] = 0ull;
    for (int kt = 0; kt < 128; kt += 32){
      #pragma unroll
      for (int i=0;i<8;i++){
        int f = i*128 + tid;
        int r = f >> 5, c4 = f & 31;
        float4 v = *(const float4*)&img[((size_t)(b*(NT+1) + 1 + keeps[kt + r]))*CD + ctile + c4*4];
        *(float4*)&Bs[r][c4*4] = v;
      }
      __syncthreads();
      #pragma unroll
      for (int kk=0; kk<32; kk++){
        const ull* bp = (const ull*)&Bs[kk][0];
        ull B0 = bp[colLane], B1 = bp[colLane+16], B2 = bp[colLane+32], B3 = bp[colLane+48];
        const ull* wr = &wdup[kt+kk][tg*5];
        #pragma unroll
        for (int i=0;i<5;i++){
          ull W = wr[i];
          acc[i][0] = fma2(W, B0, acc[i][0]);
          acc[i][1] = fma2(W, B1, acc[i][1]);
          acc[i][2] = fma2(W, B2, acc[i][2]);
          acc[i][3] = fma2(W, B3, acc[i][3]);
        }
      }
      __syncthreads();
    }
    #pragma unroll
    for (int i=0;i<5;i++){
      int t = tg*5 + i;
      if (t < NSEL){
        #pragma unroll
        for (int u=0;u<4;u++){
          float lo, hi; upk2(acc[i][u], lo, hi);
          *(float2*)&g_toks[((size_t)jb*NTOKS + 1 + t)*CD + ctile + 2*(colLane + 16*u)]
              = make_float2(lo, hi);
        }
      }
    }
  }
  for (int c = tid; c < CD; c += 128){
    g_toks[((size_t)jb*NTOKS + 0)*CD + c]  = img[((size_t)(b*(NT+1)))*CD + c];
    g_toks[((size_t)jb*NTOKS + 40)*CD + c] = g_extra[(size_t)jb*CD + c];
  }
}

// ----- c2t v2: k-pair packed GEMM + fused token-norms + leaky + reductions ---
__global__ void __launch_bounds__(128) k_c2t(float* __restrict__ out){
  __shared__ __align__(16) ull As2[16][34];
  __shared__ __align__(16) ull Bs2[16][42];
  __shared__ float c2t[MW][48];
  __shared__ float inv[48];
  __shared__ float sqarr[NTOKS][8];
  __shared__ float redA[MW], redB[NTOKS];
  int jb = blockIdx.x; int j = jb / BV, b = jb % BV;
  int tid = threadIdx.x;
  int w = tid >> 5, lane = tid & 31;
  ull acc0[8], acc1[8];
  #pragma unroll
  for (int i=0;i<8;i++){ acc0[i]=0ull; acc1[i]=0ull; }
  float sq0 = 0.f, sq1 = 0.f, sq2 = 0.f;
  for (int kt = 0; kt < CD; kt += 32){
    {
      int m = tid >> 2;
      #pragma unroll
      for (int h=0;h<2;h++){
        int q = (tid & 3) + 4*h;
        float4 v = *(const float4*)&g_capn[((size_t)(j*MW + m))*CD + kt + q*4];
        As2[2*q]  [m] = pk2(v.x, v.y);
        As2[2*q+1][m] = pk2(v.z, v.w);
      }
    }
    #pragma unroll
    for (int it=0; it<3; it++){
      int f = it*128 + tid;
      if (f < NTOKS*8){
        int t = f >> 3, q = f & 7;
        float4 v = *(const float4*)&g_toks[((size_t)jb*NTOKS + t)*CD + kt + q*4];
        Bs2[2*q]  [t] = pk2(v.x, v.y);
        Bs2[2*q+1][t] = pk2(v.z, v.w);
        float p = v.x*v.x + v.y*v.y + v.z*v.z + v.w*v.w;
        if (it==0) sq0 += p; else if (it==1) sq1 += p; else sq2 += p;
      }
    }
    __syncthreads();
    #pragma unroll
    for (int kk2=0; kk2<16; kk2++){
      ull a[8];
      #pragma unroll
      for (int i=0;i<8;i++) a[i] = As2[kk2][w + 4*i];
      ull B0 = Bs2[kk2][lane];
      #pragma unroll
      for (int i=0;i<8;i++) acc0[i] = fma2(a[i], B0, acc0[i]);
      if (lane < 9){
        ull B1 = Bs2[kk2][32 + lane];
        #pragma unroll
        for (int i=0;i<8;i++) acc1[i] = fma2(a[i], B1, acc1[i]);
      }
    }
    __syncthreads();
  }
  sqarr[tid>>3][tid&7] = sq0;
  {
    int f1 = 128 + tid;
    sqarr[f1>>3][f1&7] = sq1;
    int f2 = 256 + tid;
    if (f2 < NTOKS*8) sqarr[f2>>3][f2&7] = sq2;
  }
  __syncthreads();
  if (tid < 48){
    if (tid < NTOKS){
      float s = 0.f;
      #pragma unroll
      for (int q=0;q<8;q++) s += sqarr[tid][q];
      inv[tid] = 1.0f / fmaxf(sqrtf(s), 1e-12f);
    } else inv[tid] = 0.f;
  }
  __syncthreads();
  {
    float iv0 = inv[lane];
    float iv1 = (lane < 9) ? inv[32 + lane] : 0.f;
    #pragma unroll
    for (int i=0;i<8;i++){
      int row = w + 4*i;
      float lo, hi; upk2(acc0[i], lo, hi);
      float v0 = (lo + hi) * iv0;
      c2t[row][lane] = (v0 >= 0.f) ? v0 : 0.1f*v0;
      if (lane < 9){
        upk2(acc1[i], lo, hi);
        float v1 = (lo + hi) * iv1;
        c2t[row][32 + lane] = (v1 >= 0.f) ? v1 : 0.1f*v1;
      }
    }
  }
  __syncthreads();
  if (tid < MW){
    float mx = -3.4e38f;
    for (int t=0;t<NTOKS;t++) mx = fmaxf(mx, c2t[tid][t]);
    redA[tid] = mx;
  }
  if (tid < NTOKS){
    float mx = -3.4e38f;
    for (int m=0;m<MW;m++) mx = fmaxf(mx, c2t[m][tid]);
    redB[tid] = mx;
  }
  __syncthreads();
  if (tid == 0){
    float row = 0.f; for (int m=0;m<MW;m++) row += redA[m];
    row *= (1.0f/MW);
    float col = 0.f; for (int t=0;t<NTOKS;t++) col += redB[t];
    col *= (1.0f/NTOKS);
    out[b*BT + j] = row + col;
  }
}

// ----------------------------- launcher --------------------------------------
extern "C" void kernel_launch(void* const* d_in, const int* in_sizes, int n_in,
                              void* d_out, int out_size){
  const float* img   = (const float*)d_in[0];
  const float* cap   = (const float*)d_in[1];
  const float* lng   = (const float*)d_in[3];
  const float* lnb   = (const float*)d_in[4];
  const float* w1    = (const float*)d_in[5];
  const float* b1    = (const float*)d_in[6];
  const float* w2    = (const float*)d_in[7];
  const float* b2    = (const float*)d_in[8];
  const float* scale = (const float*)d_in[9];
  float* out = (float*)d_out;

  k_capnorm<<<BT*MW, 128>>>(cap);
  k_spnorm<<<BV*NT, 128>>>(img);
  k_glosim<<<BV, 256>>>(img);
  k_stats<<<NTOK/8, 256>>>(img);
  k_mlp1<<<dim3(NTOK/64, 2), 256>>>(img, lng, lnb, w1, b1);
  k_mlp2<<<NTOK/64, 256>>>(w2, b2);
  k_score<<<NPAIR, 128>>>();
  k_sort<<<NPAIR, 256>>>(img, scale);
  k_aggr<<<NPAIR, 128>>>(img);
  k_c2t<<<NPAIR, 128>>>(out);
}

// round 16
// speedup vs baseline: 1.4663x; 1.0034x over previous
#include <cuda_runtime.h>
#include <math.h>

#define BV 48
#define BT 48
#define MW 32
#define NT 196
#define CD 512
#define HIDN 102
#define NKEEP 98
#define NSEL 39
#define NTOKS 41
#define NPAIR (BT*BV)
#define NTOK (BV*NT)

typedef unsigned long long ull;

// ---------------- scratch (device globals) ----------------------------------
__device__ float g_capn[BT*MW*CD];
__device__ float g_spn[BV*NT*CD];
__device__ float g_sim[BV*NT];
__device__ float g_score[NPAIR*NT];
__device__ int   g_keep[NPAIR*NKEEP];
__device__ float g_extra[NPAIR*CD];
__device__ float g_tmu[NTOK];
__device__ float g_trstd[NTOK];
__device__ float g_h[(size_t)NTOK*HIDN];
__device__ float g_tlog[(size_t)NTOK*NSEL];
__device__ float g_wt[(size_t)NPAIR*NKEEP*NSEL];
__device__ float g_toks[(size_t)NPAIR*NTOKS*CD];

__device__ __forceinline__ float warpSum(float v){
  #pragma unroll
  for (int o=16;o;o>>=1) v += __shfl_xor_sync(0xffffffffu, v, o);
  return v;
}
__device__ __forceinline__ float warpMax(float v){
  #pragma unroll
  for (int o=16;o;o>>=1) v = fmaxf(v, __shfl_xor_sync(0xffffffffu, v, o));
  return v;
}
__device__ __forceinline__ ull pk2(float lo, float hi){
  ull r; asm("mov.b64 %0, {%1,%2};" : "=l"(r) : "f"(lo), "f"(hi)); return r;
}
__device__ __forceinline__ void upk2(ull v, float& lo, float& hi){
  asm("mov.b64 {%0,%1}, %2;" : "=f"(lo), "=f"(hi) : "l"(v));
}
__device__ __forceinline__ ull fma2(ull a, ull b, ull c){
  ull d; asm("fma.rn.f32x2 %0, %1, %2, %3;" : "=l"(d) : "l"(a), "l"(b), "l"(c)); return d;
}

// ------------------------- caption row l2norm -------------------------------
__global__ void k_capnorm(const float* __restrict__ cap){
  int row = blockIdx.x; int tid = threadIdx.x; // 128
  const float4* src = (const float4*)(cap + (size_t)row*CD);
  float4 v = src[tid];
  float ss = v.x*v.x + v.y*v.y + v.z*v.z + v.w*v.w;
  ss = warpSum(ss);
  __shared__ float rs[4]; __shared__ float s_inv;
  if ((tid&31)==0) rs[tid>>5] = ss;
  __syncthreads();
  if (tid==0){ float s = rs[0]+rs[1]+rs[2]+rs[3]; s_inv = 1.0f/fmaxf(sqrtf(s), 1e-12f); }
  __syncthreads();
  float inv = s_inv;
  ((float4*)(g_capn + (size_t)row*CD))[tid] = make_float4(v.x*inv, v.y*inv, v.z*inv, v.w*inv);
}

// --------- spatial row l2norm + LN stats fused (one img read) ----------------
__global__ void k_spnorm(const float* __restrict__ img){
  int row = blockIdx.x; int b = row / NT, n = row % NT;
  int tid = threadIdx.x; // 128
  const float4* src = (const float4*)(img + ((size_t)(b*(NT+1) + 1 + n))*CD);
  float4 v = src[tid];
  float ss = v.x*v.x + v.y*v.y + v.z*v.z + v.w*v.w;
  float sm = v.x + v.y + v.z + v.w;
  ss = warpSum(ss);
  sm = warpSum(sm);
  __shared__ float rs[4], rm[4]; __shared__ float s_inv;
  if ((tid&31)==0){ rs[tid>>5] = ss; rm[tid>>5] = sm; }
  __syncthreads();
  if (tid==0){
    float s = rs[0]+rs[1]+rs[2]+rs[3];
    float m = rm[0]+rm[1]+rm[2]+rm[3];
    s_inv = 1.0f/fmaxf(sqrtf(s), 1e-12f);
    float mu = m * (1.0f/CD);
    float var = s * (1.0f/CD) - mu*mu;
    g_tmu[row]   = mu;
    g_trstd[row] = rsqrtf(var + 1e-5f);
  }
  __syncthreads();
  float inv = s_inv;
  ((float4*)(g_spn + (size_t)row*CD))[tid] = make_float4(v.x*inv, v.y*inv, v.z*inv, v.w*inv);
}

// ------------- glo = l2norm(mean over tokens); s_im = glo . spn --------------
__global__ void k_glosim(const float* __restrict__ img){
  int b = blockIdx.x; int tid = threadIdx.x; // 256
  __shared__ float sg[CD];
  __shared__ float rs[8]; __shared__ float s_inv;
  float a0 = 0.f, a1 = 0.f;
  for (int n = 0; n < NT; n++){
    const float* r = img + ((size_t)(b*(NT+1) + 1 + n))*CD;
    a0 += r[tid]; a1 += r[tid+256];
  }
  a0 *= (1.0f/NT); a1 *= (1.0f/NT);
  float ss = a0*a0 + a1*a1;
  ss = warpSum(ss);
  if ((tid&31)==0) rs[tid>>5] = ss;
  __syncthreads();
  if (tid==0){ float s=0.f; for (int i=0;i<8;i++) s += rs[i]; s_inv = 1.0f/fmaxf(sqrtf(s),1e-12f); }
  __syncthreads();
  float inv = s_inv;
  sg[tid]       = a0*inv;
  sg[tid + 256] = a1*inv;
  __syncthreads();
  int wid = tid >> 5, lane = tid & 31;
  const float4* g4 = (const float4*)sg;
  for (int n = wid; n < NT; n += 8){
    const float4* sp = (const float4*)(g_spn + ((size_t)(b*NT + n))*CD);
    float d = 0.f;
    #pragma unroll
    for (int i=0;i<4;i++){
      float4 a = sp[lane + i*32]; float4 c = g4[lane + i*32];
      d += a.x*c.x + a.y*c.y + a.z*c.z + a.w*c.w;
    }
    d = warpSum(d);
    if (lane==0) g_sim[b*NT + n] = d;
  }
}

// -------- GEMM1 (per-token): H = gelu( LN(tok) @ w1 + b1 ), 9408 x 102 ------
__global__ void k_mlp1(const float* __restrict__ img,
                       const float* __restrict__ lng, const float* __restrict__ lnb,
                       const float* __restrict__ w1,  const float* __restrict__ b1){
  __shared__ __align__(16) float As[32][68];
  __shared__ __align__(16) float Bs[32][68];
  __shared__ int   sIdx[64];
  __shared__ float sMu[64], sRstd[64];
  int rt = blockIdx.x * 64;
  int colTile = blockIdx.y * 64;
  int tid = threadIdx.x;
  if (tid < 64){
    int row = rt + tid;
    int b = row / NT, n = row % NT;
    sIdx[tid] = b*(NT+1) + 1 + n;
    sMu[tid] = g_tmu[row]; sRstd[tid] = g_trstd[row];
  }
  __syncthreads();
  ull acc[4][2];
  #pragma unroll
  for (int i=0;i<4;i++){ acc[i][0]=0ull; acc[i][1]=0ull; }
  int ty = tid >> 4, tx = tid & 15;
  for (int kt = 0; kt < CD; kt += 32){
    #pragma unroll
    for (int i=0;i<8;i++){
      int f = i*256 + tid;
      int r = f >> 5, c = f & 31;
      float v = img[(size_t)sIdx[r]*CD + kt + c];
      As[c][r] = (v - sMu[r]) * sRstd[r] * __ldg(&lng[kt+c]) + __ldg(&lnb[kt+c]);
    }
    #pragma unroll
    for (int i=0;i<8;i++){
      int f = i*256 + tid;
      int kk = f >> 6, nn = f & 63;
      int col = colTile + nn;
      Bs[kk][nn] = (col < HIDN) ? w1[(size_t)(kt+kk)*HIDN + col] : 0.f;
    }
    __syncthreads();
    #pragma unroll
    for (int kk=0; kk<32; kk++){
      float4 a = *(const float4*)&As[kk][ty<<2];
      const ull* bp = (const ull*)&Bs[kk][tx<<2];
      ull B0 = bp[0], B1 = bp[1];
      ull A0 = pk2(a.x,a.x), A1 = pk2(a.y,a.y), A2 = pk2(a.z,a.z), A3 = pk2(a.w,a.w);
      acc[0][0]=fma2(A0,B0,acc[0][0]); acc[0][1]=fma2(A0,B1,acc[0][1]);
      acc[1][0]=fma2(A1,B0,acc[1][0]); acc[1][1]=fma2(A1,B1,acc[1][1]);
      acc[2][0]=fma2(A2,B0,acc[2][0]); acc[2][1]=fma2(A2,B1,acc[2][1]);
      acc[3][0]=fma2(A3,B0,acc[3][0]); acc[3][1]=fma2(A3,B1,acc[3][1]);
    }
    __syncthreads();
  }
  #pragma unroll
  for (int i=0;i<4;i++){
    int row = rt + (ty<<2) + i;
    #pragma unroll
    for (int h=0;h<2;h++){
      float lo, hi; upk2(acc[i][h], lo, hi);
      float vv[2] = {lo, hi};
      #pragma unroll
      for (int q=0;q<2;q++){
        int col = colTile + (tx<<2) + h*2 + q;
        if (col < HIDN){
          float x = vv[q] + __ldg(&b1[col]);
          float gl = 0.5f * x * (1.0f + erff(x * 0.70710678118654752f));
          g_h[(size_t)row*HIDN + col] = gl;
        }
      }
    }
  }
}

// ------------- GEMM2 (per-token): tlog = H @ w2 + b2, 9408 x 39 --------------
__global__ void k_mlp2(const float* __restrict__ w2, const float* __restrict__ b2){
  __shared__ float Hs[64][104];
  __shared__ __align__(16) float w2s[HIDN][40];
  int rt = blockIdx.x * 64;
  int tid = threadIdx.x;
  for (int f = tid; f < 64*HIDN; f += 256){
    int r = f / HIDN, c = f - r*HIDN;
    Hs[r][c] = g_h[(size_t)rt*HIDN + f];
  }
  for (int f = tid; f < HIDN*NSEL; f += 256){
    int h = f / NSEL, t = f - h*NSEL;
    w2s[h][t] = w2[f];
  }
  for (int f = tid; f < HIDN; f += 256) w2s[f][39] = 0.f;
  __syncthreads();
  int r = tid >> 2, g = tid & 3;
  ull acc[5] = {0ull,0ull,0ull,0ull,0ull};
  for (int c = 0; c < HIDN; c++){
    float h = Hs[r][c];
    ull H = pk2(h,h);
    const ull* wp = (const ull*)&w2s[c][0];
    #pragma unroll
    for (int u=0;u<5;u++) acc[u] = fma2(H, wp[g + 4*u], acc[u]);
  }
  #pragma unroll
  for (int u=0;u<5;u++){
    float lo, hi; upk2(acc[u], lo, hi);
    int t0 = 2*(g + 4*u);
    g_tlog[(size_t)(rt + r)*NSEL + t0] = lo + __ldg(&b2[t0]);
    if (t0 + 1 < NSEL)
      g_tlog[(size_t)(rt + r)*NSEL + t0 + 1] = hi + __ldg(&b2[t0+1]);
  }
}

// ---- score v4 (known-good): k-pair fma2, 128 threads ------------------------
__global__ void __launch_bounds__(128) k_score(){
  __shared__ __align__(16) ull As2[16][34];
  __shared__ __align__(16) ull Bs2[16][201];
  __shared__ float red[4][196];
  int jb = blockIdx.x; int j = jb / BV, b = jb % BV;
  int tid = threadIdx.x;
  int w = tid >> 5, lane = tid & 31;
  ull acc[8][6], accT[8];
  #pragma unroll
  for (int i=0;i<8;i++){
    #pragma unroll
    for (int v=0;v<6;v++) acc[i][v] = 0ull;
    accT[i] = 0ull;
  }
  for (int kt = 0; kt < CD; kt += 32){
    {
      int m = tid >> 2;
      #pragma unroll
      for (int h=0;h<2;h++){
        int q = (tid & 3) + 4*h;
        float4 v = *(const float4*)&g_capn[((size_t)(j*MW + m))*CD + kt + q*4];
        As2[2*q]  [m] = pk2(v.x, v.y);
        As2[2*q+1][m] = pk2(v.z, v.w);
      }
    }
    for (int f = tid; f < NT*8; f += 128){
      int t = f >> 3, q = f & 7;
      float4 v = *(const float4*)&g_spn[((size_t)(b*NT + t))*CD + kt + q*4];
      Bs2[2*q]  [t] = pk2(v.x, v.y);
      Bs2[2*q+1][t] = pk2(v.z, v.w);
    }
    __syncthreads();
    #pragma unroll
    for (int kk2=0; kk2<16; kk2++){
      ull a[8];
      #pragma unroll
      for (int i=0;i<8;i++) a[i] = As2[kk2][w + 4*i];
      const ull* brow = &Bs2[kk2][0];
      #pragma unroll
      for (int v=0;v<6;v++){
        ull B = brow[lane + 32*v];
        #pragma unroll
        for (int i=0;i<8;i++) acc[i][v] = fma2(a[i], B, acc[i][v]);
      }
      if (lane < 4){
        ull B = brow[192 + lane];
        #pragma unroll
        for (int i=0;i<8;i++) accT[i] = fma2(a[i], B, accT[i]);
      }
    }
    __syncthreads();
  }
  #pragma unroll
  for (int v=0;v<6;v++){
    float mx = -3.4e38f;
    #pragma unroll
    for (int i=0;i<8;i++){
      float lo, hi; upk2(acc[i][v], lo, hi);
      mx = fmaxf(mx, lo + hi);
    }
    red[w][lane + 32*v] = mx;
  }
  if (lane < 4){
    float mx = -3.4e38f;
    #pragma unroll
    for (int i=0;i<8;i++){
      float lo, hi; upk2(accT[i], lo, hi);
      mx = fmaxf(mx, lo + hi);
    }
    red[w][192 + lane] = mx;
  }
  __syncthreads();
  for (int t = tid; t < NT; t += 128){
    float mx = fmaxf(fmaxf(red[0][t], red[1][t]), fmaxf(red[2][t], red[3][t]));
    g_score[(size_t)jb*NT + t] = g_sim[b*NT + t] + mx;
  }
}

// ---- per (j,b): hybrid bitonic sort + extra token + fused softmax -----------
__global__ void k_sort(const float* __restrict__ img, const float* __restrict__ scale){
  __shared__ float svals[256];
  __shared__ int   sidxs[256];
  __shared__ float wbuf[NKEEP];
  __shared__ float rs[8]; __shared__ float s_tot;
  __shared__ float s[NKEEP][40];
  int jb = blockIdx.x; int b = jb % BV;
  int tid = threadIdx.x;
  int w = tid >> 5, lane = tid & 31;
  float v = (tid < NT) ? -g_score[(size_t)jb*NT + tid] : 3.4e38f;
  int id = tid;
  const unsigned FULL = 0xffffffffu;
  for (int k = 2; k <= 256; k <<= 1){
    for (int sdist = k >> 1; sdist > 0; sdist >>= 1){
      bool up = ((tid & k) == 0);
      bool lower = ((tid & sdist) == 0);
      if (sdist >= 32){
        svals[tid] = v; sidxs[tid] = id;
        __syncthreads();
        int p = tid ^ sdist;
        float ov = svals[p]; int oi = sidxs[p];
        bool swap = lower ? ((v > ov) == up) : ((ov > v) == up);
        if (swap){ v = ov; id = oi; }
        __syncthreads();
      } else {
        float ov = __shfl_xor_sync(FULL, v, sdist);
        int oi   = __shfl_xor_sync(FULL, id, sdist);
        bool swap = lower ? ((v > ov) == up) : ((ov > v) == up);
        if (swap){ v = ov; id = oi; }
      }
    }
  }
  svals[tid] = v; sidxs[tid] = id;
  __syncthreads();
  if (tid < NKEEP) g_keep[(size_t)jb*NKEEP + tid] = sidxs[tid];
  float e = 0.f;
  if (tid < NKEEP){ e = expf(svals[NKEEP] - svals[NKEEP + tid]); wbuf[tid] = e; }
  float vv = warpSum(e);
  if ((tid&31)==0) rs[tid>>5] = vv;
  __syncthreads();
  if (tid==0){ float ssum=0.f; for (int i=0;i<8;i++) ssum += rs[i]; s_tot = ssum; }
  __syncthreads();
  float invq = 1.0f / s_tot;
  {
    float a0 = 0.f, a1 = 0.f;
    for (int i = 0; i < NKEEP; i++){
      float wq = wbuf[i];
      const float* r = img + ((size_t)(b*(NT+1) + 1 + sidxs[NKEEP+i]))*CD;
      a0 += wq * r[tid]; a1 += wq * r[tid+256];
    }
    g_extra[(size_t)jb*CD + tid]       = a0*invq;
    g_extra[(size_t)jb*CD + tid + 256] = a1*invq;
  }
  float sc = __ldg(scale);
  for (int f = tid; f < NKEEP*NSEL; f += 256){
    int k = f / NSEL, t = f - k*NSEL;
    s[k][t] = g_tlog[(size_t)(b*NT + sidxs[k])*NSEL + t] * sc;
  }
  __syncthreads();
  for (int t = w; t < NSEL; t += 8){
    float v0 = s[lane][t], v1 = s[lane+32][t], v2 = s[lane+64][t];
    float v3 = (lane < 2) ? s[lane+96][t] : -3.4e38f;
    float mx = warpMax(fmaxf(fmaxf(v0,v1), fmaxf(v2,v3)));
    float e0 = expf(v0-mx), e1 = expf(v1-mx), e2 = expf(v2-mx);
    float e3 = (lane < 2) ? expf(v3-mx) : 0.f;
    float tot = warpSum(e0+e1+e2+e3);
    float inv2 = 1.0f / tot;
    s[lane][t] = e0*inv2; s[lane+32][t] = e1*inv2; s[lane+64][t] = e2*inv2;
    if (lane < 2) s[lane+96][t] = e3*inv2;
  }
  __syncthreads();
  for (int f = tid; f < NKEEP*NSEL; f += 256){
    int k = f / NSEL, t = f - k*NSEL;
    g_wt[(size_t)jb*NKEEP*NSEL + f] = s[k][t];
  }
}

// ------- aggregation multi-tile: paired B-ull loads, float4 stores -----------
__global__ void __launch_bounds__(128) k_aggr(const float* __restrict__ img){
  __shared__ __align__(16) ull   wdup[128][40];
  __shared__ __align__(16) float Bs[32][132];
  __shared__ int keeps[128];
  int jb = blockIdx.x; int b = jb % BV;
  int tid = threadIdx.x;    // 128
  for (int f = tid; f < NKEEP*NSEL; f += 128){
    int k = f / NSEL, t = f - k*NSEL;
    float w = g_wt[(size_t)jb*NKEEP*NSEL + f];
    wdup[k][t] = pk2(w, w);
  }
  wdup[tid][39] = 0ull;
  for (int f = tid; f < 30*40; f += 128){
    int k = NKEEP + f/40, t = f%40;
    wdup[k][t] = 0ull;
  }
  keeps[tid] = g_keep[(size_t)jb*NKEEP + ((tid < NKEEP) ? tid : 0)];
  __syncthreads();
  int colLane = tid & 15;
  int tg = tid >> 4;          // 0..7 token groups (5 t each)
  for (int ctile = 0; ctile < CD; ctile += 128){
    ull acc[5][4];
    #pragma unroll
    for (int i=0;i<5;i++)
      #pragma unroll
      for (int u=0;u<4;u++) acc[i][u] = 0ull;
    for (int kt = 0; kt < 128; kt += 32){
      #pragma unroll
      for (int i=0;i<8;i++){
        int f = i*128 + tid;
        int r = f >> 5, c4 = f & 31;
        float4 v = *(const float4*)&img[((size_t)(b*(NT+1) + 1 + keeps[kt + r]))*CD + ctile + c4*4];
        *(float4*)&Bs[r][c4*4] = v;
      }
      __syncthreads();
      #pragma unroll
      for (int kk=0; kk<32; kk++){
        const ull* bp = (const ull*)&Bs[kk][0];
        ulonglong2 b01 = *(const ulonglong2*)&bp[2*colLane];
        ulonglong2 b23 = *(const ulonglong2*)&bp[32 + 2*colLane];
        const ull* wr = &wdup[kt+kk][tg*5];
        #pragma unroll
        for (int i=0;i<5;i++){
          ull W = wr[i];
          acc[i][0] = fma2(W, b01.x, acc[i][0]);
          acc[i][1] = fma2(W, b01.y, acc[i][1]);
          acc[i][2] = fma2(W, b23.x, acc[i][2]);
          acc[i][3] = fma2(W, b23.y, acc[i][3]);
        }
      }
      __syncthreads();
    }
    #pragma unroll
    for (int i=0;i<5;i++){
      int t = tg*5 + i;
      if (t < NSEL){
        float4 o0, o1;
        upk2(acc[i][0], o0.x, o0.y);
        upk2(acc[i][1], o0.z, o0.w);
        upk2(acc[i][2], o1.x, o1.y);
        upk2(acc[i][3], o1.z, o1.w);
        float* dst = &g_toks[((size_t)jb*NTOKS + 1 + t)*CD + ctile];
        *(float4*)(dst + 4*colLane)       = o0;
        *(float4*)(dst + 64 + 4*colLane)  = o1;
      }
    }
  }
  for (int c = tid; c < CD; c += 128){
    g_toks[((size_t)jb*NTOKS + 0)*CD + c]  = img[((size_t)(b*(NT+1)))*CD + c];
    g_toks[((size_t)jb*NTOKS + 40)*CD + c] = g_extra[(size_t)jb*CD + c];
  }
}

// ----- c2t v2: k-pair packed GEMM + fused token-norms + leaky + reductions ---
__global__ void __launch_bounds__(128) k_c2t(float* __restrict__ out){
  __shared__ __align__(16) ull As2[16][34];
  __shared__ __align__(16) ull Bs2[16][42];
  __shared__ float c2t[MW][48];
  __shared__ float inv[48];
  __shared__ float sqarr[NTOKS][8];
  __shared__ float redA[MW], redB[NTOKS];
  int jb = blockIdx.x; int j = jb / BV, b = jb % BV;
  int tid = threadIdx.x;
  int w = tid >> 5, lane = tid & 31;
  ull acc0[8], acc1[8];
  #pragma unroll
  for (int i=0;i<8;i++){ acc0[i]=0ull; acc1[i]=0ull; }
  float sq0 = 0.f, sq1 = 0.f, sq2 = 0.f;
  for (int kt = 0; kt < CD; kt += 32){
    {
      int m = tid >> 2;
      #pragma unroll
      for (int h=0;h<2;h++){
        int q = (tid & 3) + 4*h;
        float4 v = *(const float4*)&g_capn[((size_t)(j*MW + m))*CD + kt + q*4];
        As2[2*q]  [m] = pk2(v.x, v.y);
        As2[2*q+1][m] = pk2(v.z, v.w);
      }
    }
    #pragma unroll
    for (int it=0; it<3; it++){
      int f = it*128 + tid;
      if (f < NTOKS*8){
        int t = f >> 3, q = f & 7;
        float4 v = *(const float4*)&g_toks[((size_t)jb*NTOKS + t)*CD + kt + q*4];
        Bs2[2*q]  [t] = pk2(v.x, v.y);
        Bs2[2*q+1][t] = pk2(v.z, v.w);
        float p = v.x*v.x + v.y*v.y + v.z*v.z + v.w*v.w;
        if (it==0) sq0 += p; else if (it==1) sq1 += p; else sq2 += p;
      }
    }
    __syncthreads();
    #pragma unroll
    for (int kk2=0; kk2<16; kk2++){
      ull a[8];
      #pragma unroll
      for (int i=0;i<8;i++) a[i] = As2[kk2][w + 4*i];
      ull B0 = Bs2[kk2][lane];
      #pragma unroll
      for (int i=0;i<8;i++) acc0[i] = fma2(a[i], B0, acc0[i]);
      if (lane < 9){
        ull B1 = Bs2[kk2][32 + lane];
        #pragma unroll
        for (int i=0;i<8;i++) acc1[i] = fma2(a[i], B1, acc1[i]);
      }
    }
    __syncthreads();
  }
  sqarr[tid>>3][tid&7] = sq0;
  {
    int f1 = 128 + tid;
    sqarr[f1>>3][f1&7] = sq1;
    int f2 = 256 + tid;
    if (f2 < NTOKS*8) sqarr[f2>>3][f2&7] = sq2;
  }
  __syncthreads();
  if (tid < 48){
    if (tid < NTOKS){
      float s = 0.f;
      #pragma unroll
      for (int q=0;q<8;q++) s += sqarr[tid][q];
      inv[tid] = 1.0f / fmaxf(sqrtf(s), 1e-12f);
    } else inv[tid] = 0.f;
  }
  __syncthreads();
  {
    float iv0 = inv[lane];
    float iv1 = (lane < 9) ? inv[32 + lane] : 0.f;
    #pragma unroll
    for (int i=0;i<8;i++){
      int row = w + 4*i;
      float lo, hi; upk2(acc0[i], lo, hi);
      float v0 = (lo + hi) * iv0;
      c2t[row][lane] = (v0 >= 0.f) ? v0 : 0.1f*v0;
      if (lane < 9){
        upk2(acc1[i], lo, hi);
        float v1 = (lo + hi) * iv1;
        c2t[row][32 + lane] = (v1 >= 0.f) ? v1 : 0.1f*v1;
      }
    }
  }
  __syncthreads();
  if (tid < MW){
    float mx = -3.4e38f;
    for (int t=0;t<NTOKS;t++) mx = fmaxf(mx, c2t[tid][t]);
    redA[tid] = mx;
  }
  if (tid < NTOKS){
    float mx = -3.4e38f;
    for (int m=0;m<MW;m++) mx = fmaxf(mx, c2t[m][tid]);
    redB[tid] = mx;
  }
  __syncthreads();
  if (tid == 0){
    float row = 0.f; for (int m=0;m<MW;m++) row += redA[m];
    row *= (1.0f/MW);
    float col = 0.f; for (int t=0;t<NTOKS;t++) col += redB[t];
    col *= (1.0f/NTOKS);
    out[b*BT + j] = row + col;
  }
}

// ----------------------------- launcher --------------------------------------
extern "C" void kernel_launch(void* const* d_in, const int* in_sizes, int n_in,
                              void* d_out, int out_size){
  const float* img   = (const float*)d_in[0];
  const float* cap   = (const float*)d_in[1];
  const float* lng   = (const float*)d_in[3];
  const float* lnb   = (const float*)d_in[4];
  const float* w1    = (const float*)d_in[5];
  const float* b1    = (const float*)d_in[6];
  const float* w2    = (const float*)d_in[7];
  const float* b2    = (const float*)d_in[8];
  const float* scale = (const float*)d_in[9];
  float* out = (float*)d_out;

  k_capnorm<<<BT*MW, 128>>>(cap);
  k_spnorm<<<BV*NT, 128>>>(img);
  k_glosim<<<BV, 256>>>(img);
  k_mlp1<<<dim3(NTOK/64, 2), 256>>>(img, lng, lnb, w1, b1);
  k_mlp2<<<NTOK/64, 256>>>(w2, b2);
  k_score<<<NPAIR, 128>>>();
  k_sort<<<NPAIR, 256>>>(img, scale);
  k_aggr<<<NPAIR, 128>>>(img);
  k_c2t<<<NPAIR, 128>>>(out);
}